// round 1
// baseline (speedup 1.0000x reference)
#include <cuda_runtime.h>

#define DIM (1u<<22)

// Persistent scratch (allowed: __device__ globals, no allocation)
__device__ float2 g_bufA[DIM];
__device__ float2 g_bufB[DIM];
__device__ float2 g_U[4*22*4];   // [layer][qubit][4] fused U = RZ*RY*RX
__device__ double g_acc[23];     // z[0..21], total at [22]

__device__ __forceinline__ int SWZ(int a){ return a ^ ((a>>4)&15); }

__device__ __forceinline__ float2 cxmul(float2 a, float2 b){
  return make_float2(a.x*b.x - a.y*b.y, a.x*b.y + a.y*b.x);
}

// Apply 2x2 gate on register-bit J over 16 register-resident amplitudes.
template<int J>
__device__ __forceinline__ void gate16(float2 (&r)[16], const float2* __restrict__ U){
  const float2 u00=U[0], u01=U[1], u10=U[2], u11=U[3];
#pragma unroll
  for (int i=0;i<16;i++){
    if ((i & (1<<J)) == 0){
      const int j2 = i | (1<<J);
      const float2 a = r[i], b = r[j2];
      float2 na, nb;
      na.x = u00.x*a.x - u00.y*a.y + u01.x*b.x - u01.y*b.y;
      na.y = u00.x*a.y + u00.y*a.x + u01.x*b.y + u01.y*b.x;
      nb.x = u10.x*a.x - u10.y*a.y + u11.x*b.x - u11.y*b.y;
      nb.y = u10.x*a.y + u10.y*a.x + u11.x*b.y + u11.y*b.x;
      r[i]=na; r[j2]=nb;
    }
  }
}

// ---------------------------------------------------------------------------
// Prep: zero accumulators, build 88 fused gate matrices U = RZ * RY * RX
// ---------------------------------------------------------------------------
__global__ void k_prep(const float* __restrict__ params){
  int i = threadIdx.x;
  if (i < 23) g_acc[i] = 0.0;
  if (i < 88){
    float tx = 0.5f*params[i*3+0];
    float ty = 0.5f*params[i*3+1];
    float tz = 0.5f*params[i*3+2];
    float cx,sx,cy,sy,cz,sz;
    sincosf(tx,&sx,&cx); sincosf(ty,&sy,&cy); sincosf(tz,&sz,&cz);
    // M = RY*RX
    float2 M00 = make_float2( cy*cx,  sy*sx);
    float2 M01 = make_float2(-sy*cx, -cy*sx);
    float2 M10 = make_float2( sy*cx, -cy*sx);
    float2 M11 = make_float2( cy*cx, -sy*sx);
    float2 em = make_float2(cz,-sz), ep = make_float2(cz,sz); // e^{-i tz}, e^{+i tz}
    float2* U = &g_U[i*4];
    U[0]=cxmul(em,M00); U[1]=cxmul(em,M01);
    U[2]=cxmul(ep,M10); U[3]=cxmul(ep,M11);
  }
}

// ---------------------------------------------------------------------------
// Pass A: gates on global bits 0..11 (qubits 21..10).
// Tile = 4096 contiguous amps. 256 thr x 16 amps. Stages of reg-resident bits:
//   M0: a=(v<<8)|t   (reg bits 8..11)  -- load mapping (coalesced)
//   M1: a=((t>>4)<<8)|(v<<4)|(t&15)    (reg bits 4..7)
//   M2: a=(t<<4)|v   (reg bits 0..3)
// then back to M0 for coalesced store.
// Layers >= 2 fuse the previous layer's CNOT ladder as a Gray-code gather:
//   in[y ^ (y>>1)].
// ---------------------------------------------------------------------------
template<bool FIRST>
__global__ void __launch_bounds__(256) k_passA(
    const float* __restrict__ sre, const float* __restrict__ sim,
    int layer, int dir)
{
  __shared__ float2 sh[4096];
  const int t = threadIdx.x;
  const unsigned base = (unsigned)blockIdx.x << 12;
  const float2* in  = dir ? g_bufB : g_bufA;
  float2*       out = dir ? g_bufA : g_bufB;
  const float2* Ub = &g_U[layer*88];
  float2 r[16];

  if (FIRST){
#pragma unroll
    for (int v=0;v<16;v++){
      unsigned y = base | ((unsigned)v<<8) | (unsigned)t;
      r[v] = make_float2(sre[y], sim[y]);
    }
  } else {
#pragma unroll
    for (int v=0;v<16;v++){
      unsigned y = base | ((unsigned)v<<8) | (unsigned)t;
      unsigned x = y ^ (y>>1);          // inverse of CNOT-ladder permutation
      r[v] = in[x];
    }
  }
  // stage M0: reg bit j -> global bit 8+j -> qubit 13-j
  gate16<0>(r, Ub + 13*4);
  gate16<1>(r, Ub + 12*4);
  gate16<2>(r, Ub + 11*4);
  gate16<3>(r, Ub + 10*4);
  // exchange M0 -> M1
#pragma unroll
  for (int v=0;v<16;v++) sh[SWZ((v<<8)|t)] = r[v];
  __syncthreads();
#pragma unroll
  for (int v=0;v<16;v++) r[v] = sh[SWZ(((t>>4)<<8)|(v<<4)|(t&15))];
  // stage M1: reg bit j -> global bit 4+j -> qubit 17-j
  gate16<0>(r, Ub + 17*4);
  gate16<1>(r, Ub + 16*4);
  gate16<2>(r, Ub + 15*4);
  gate16<3>(r, Ub + 14*4);
  // exchange M1 -> M2  (each thread rewrites exactly the slots it read)
#pragma unroll
  for (int v=0;v<16;v++) sh[SWZ(((t>>4)<<8)|(v<<4)|(t&15))] = r[v];
  __syncthreads();
#pragma unroll
  for (int v=0;v<16;v++) r[v] = sh[SWZ((t<<4)|v)];
  // stage M2: reg bit j -> global bit j -> qubit 21-j
  gate16<0>(r, Ub + 21*4);
  gate16<1>(r, Ub + 20*4);
  gate16<2>(r, Ub + 19*4);
  gate16<3>(r, Ub + 18*4);
  // exchange M2 -> M0 and coalesced store
#pragma unroll
  for (int v=0;v<16;v++) sh[SWZ((t<<4)|v)] = r[v];
  __syncthreads();
#pragma unroll
  for (int v=0;v<16;v++) r[v] = sh[SWZ((v<<8)|t)];
#pragma unroll
  for (int v=0;v<16;v++) out[base | ((unsigned)v<<8) | (unsigned)t] = r[v];
}

// ---------------------------------------------------------------------------
// Pass B: gates on global bits 12..21 (qubits 9..0). In-place.
// Tile local index a (12b) = (c<<2)|v, c = global bits 12..21, v = bits 0..1.
// CTA id = global bits 2..11.  global g = ((a>>2)<<12)|(blk<<2)|(a&3).
// Same 3 stage mappings as pass A. LAST fuses the final ladder + <Z> reduction
// (no store of the final state at all).
// ---------------------------------------------------------------------------
template<bool LAST>
__global__ void __launch_bounds__(256) k_passB(int layer, int sel)
{
  __shared__ float2 sh[4096];
  __shared__ double sacc[23];
  const int t = threadIdx.x;
  const unsigned blk = blockIdx.x;
  float2* buf = sel ? g_bufA : g_bufB;
  const float2* Ub = &g_U[layer*88];
  float2 r[16];

  if (LAST){
    if (t < 23) sacc[t] = 0.0;
  }

  // load, mapping M0: a=(v<<8)|t  ->  g = (v<<18) | ((t>>2)<<12) | (blk<<2) | (t&3)
  const unsigned gbase0 = ((unsigned)(t>>2)<<12) | (blk<<2) | (unsigned)(t&3);
#pragma unroll
  for (int v=0;v<16;v++) r[v] = buf[gbase0 | ((unsigned)v<<18)];
  // stage M0: reg bit j -> a bit 8+j -> global bit 18+j -> qubit 3-j
  gate16<0>(r, Ub + 3*4);
  gate16<1>(r, Ub + 2*4);
  gate16<2>(r, Ub + 1*4);
  gate16<3>(r, Ub + 0*4);
  // exchange M0 -> M1
#pragma unroll
  for (int v=0;v<16;v++) sh[SWZ((v<<8)|t)] = r[v];
  __syncthreads();
#pragma unroll
  for (int v=0;v<16;v++) r[v] = sh[SWZ(((t>>4)<<8)|(v<<4)|(t&15))];
  // stage M1: reg bit j -> global bit 14+j -> qubit 7-j
  gate16<0>(r, Ub + 7*4);
  gate16<1>(r, Ub + 6*4);
  gate16<2>(r, Ub + 5*4);
  gate16<3>(r, Ub + 4*4);
  // exchange M1 -> M2
#pragma unroll
  for (int v=0;v<16;v++) sh[SWZ(((t>>4)<<8)|(v<<4)|(t&15))] = r[v];
  __syncthreads();
#pragma unroll
  for (int v=0;v<16;v++) r[v] = sh[SWZ((t<<4)|v)];
  // stage M2: reg bits 2,3 -> global bits 12,13 -> qubits 9,8 (bits 0,1 payload)
  gate16<2>(r, Ub + 9*4);
  gate16<3>(r, Ub + 8*4);

  if (!LAST){
    // exchange M2 -> M0 and in-place store
#pragma unroll
    for (int v=0;v<16;v++) sh[SWZ((t<<4)|v)] = r[v];
    __syncthreads();
#pragma unroll
    for (int v=0;v<16;v++) r[v] = sh[SWZ((v<<8)|t)];
#pragma unroll
    for (int v=0;v<16;v++) buf[gbase0 | ((unsigned)v<<18)] = r[v];
  } else {
    // Fused final CNOT ladder + <Z_q> reduction.
    // Amp r[v] lives at g = (t<<14)|((v>>2)<<12)|(blk<<2)|(v&3) (mapping M2);
    // its post-ladder basis label y has y_p = XOR of g bits p..21.
    float z[22];
#pragma unroll
    for (int q=0;q<22;q++) z[q] = 0.0f;
    float tot = 0.0f;
#pragma unroll
    for (int v=0;v<16;v++){
      unsigned g = ((unsigned)t<<14) | ((unsigned)(v>>2)<<12) | (blk<<2) | (unsigned)(v&3);
      unsigned y = g; y ^= y>>1; y ^= y>>2; y ^= y>>4; y ^= y>>8; y ^= y>>16;
      float p = r[v].x*r[v].x + r[v].y*r[v].y;
      tot += p;
#pragma unroll
      for (int q=0;q<22;q++)
        z[q] += ((y >> (21-q)) & 1u) ? -p : p;
    }
    __syncthreads();   // sacc initialized
#pragma unroll
    for (int q=0;q<22;q++){
      float val = z[q];
#pragma unroll
      for (int o=16;o;o>>=1) val += __shfl_down_sync(0xffffffffu, val, o);
      if ((t & 31) == 0) atomicAdd(&sacc[q], (double)val);
    }
    {
      float val = tot;
#pragma unroll
      for (int o=16;o;o>>=1) val += __shfl_down_sync(0xffffffffu, val, o);
      if ((t & 31) == 0) atomicAdd(&sacc[22], (double)val);
    }
    __syncthreads();
    if (t < 23) atomicAdd(&g_acc[t], sacc[t]);
  }
}

__global__ void k_final(float* __restrict__ out){
  int q = threadIdx.x;
  if (q < 22) out[q] = (float)(g_acc[q] / g_acc[22]);
}

extern "C" void kernel_launch(void* const* d_in, const int* in_sizes, int n_in,
                              void* d_out, int out_size)
{
  const float* params = (const float*)d_in[0];
  const float* sre    = (const float*)d_in[1];
  const float* sim    = (const float*)d_in[2];
  float* out = (float*)d_out;

  k_prep<<<1,128>>>(params);

  // Layer 1: A writes bufA (dir=1), B in-place on bufA (sel=1)
  k_passA<true ><<<1024,256>>>(sre, sim, 0, 1);
  k_passB<false><<<1024,256>>>(0, 1);
  // Layer 2: A reads bufA -> bufB (dir=0), B on bufB (sel=0)
  k_passA<false><<<1024,256>>>(nullptr, nullptr, 1, 0);
  k_passB<false><<<1024,256>>>(1, 0);
  // Layer 3: bufB -> bufA
  k_passA<false><<<1024,256>>>(nullptr, nullptr, 2, 1);
  k_passB<false><<<1024,256>>>(2, 1);
  // Layer 4: bufA -> bufB, B fuses final ladder + reduction
  k_passA<false><<<1024,256>>>(nullptr, nullptr, 3, 0);
  k_passB<true ><<<1024,256>>>(3, 0);

  k_final<<<1,32>>>(out);
}